// round 12
// baseline (speedup 1.0000x reference)
#include <cuda_runtime.h>
#include <cuda_fp16.h>
#include <cstdint>

#define NUM_ENT   64
#define HALF      128
#define BATCH     512
#define I_PER_BLK 16
#define THREADS   256

typedef unsigned long long ull;

// ---- packed f32x2 helpers (Blackwell sm_100+) -------------------------------
__device__ __forceinline__ ull pk(float lo, float hi) {
    ull r; asm("mov.b64 %0, {%1,%2};" : "=l"(r) : "f"(lo), "f"(hi)); return r;
}
__device__ __forceinline__ ull pkc(float v) {
    unsigned u = __float_as_uint(v);
    return ((ull)u << 32) | (ull)u;
}
__device__ __forceinline__ float2 upk(ull v) {
    float2 r; asm("mov.b64 {%0,%1}, %2;" : "=f"(r.x), "=f"(r.y) : "l"(v)); return r;
}
__device__ __forceinline__ ull fma2(ull a, ull b, ull c) {
    ull d; asm("fma.rn.f32x2 %0, %1, %2, %3;" : "=l"(d) : "l"(a), "l"(b), "l"(c)); return d;
}
__device__ __forceinline__ ull add2(ull a, ull b) {
    ull d; asm("add.rn.f32x2 %0, %1, %2;" : "=l"(d) : "l"(a), "l"(b)); return d;
}
__device__ __forceinline__ ull sub2(ull a, ull b) {
    ull d; asm("sub.rn.f32x2 %0, %1, %2;" : "=l"(d) : "l"(a), "l"(b)); return d;
}
__device__ __forceinline__ ull mul2(ull a, ull b) {
    ull d; asm("mul.rn.f32x2 %0, %1, %2;" : "=l"(d) : "l"(a), "l"(b)); return d;
}

#define TANH_C3  (-0.33333334f)

__global__ __launch_bounds__(THREADS, 5)
void ace_kernel(const float* __restrict__ ctx,   // [NUM_ENT*4, BATCH]
                const float* __restrict__ Wp,    // [4, HALF]
                const float* __restrict__ bp,    // [HALF]
                const float* __restrict__ Wr,    // [5, HALF]
                const float* __restrict__ br,    // [HALF]
                float* __restrict__ out)         // [BATCH, NUM_ENT, 2*HALF]
{
    __shared__ float   s_ents[NUM_ENT * 4];                // 1 KB
    __shared__ __half2 s_a16[NUM_ENT * 64];                // 16 KB : half2 a[j][h-pair]
    __shared__ __half2 s_dd[I_PER_BLK * NUM_ENT];          // 4 KB  : h2(d,d)
    __shared__ float   s_apre[I_PER_BLK * HALF];           // 8 KB  : fp32 a for block rows
    __shared__ float2  s_P[24][64];                        // 12 KB : partials
                                                           //  [0:4)=s1 [4:8)=s2 [8:12)=s3
                                                           //  [12:16)=W0 [16:20)=W1x [20:24)=W1y
    __shared__ float   s_T0[I_PER_BLK];
    __shared__ float   s_U0[I_PER_BLK];
    __shared__ float   s_V0[I_PER_BLK];

    const int b     = blockIdx.x >> 2;
    const int iBase = (blockIdx.x & 3) * I_PER_BLK;
    const int t     = threadIdx.x;
    const int hp    = t & 63;
    const int grp   = t >> 6;
    const int wid   = t >> 5;
    const int lane  = t & 31;

    // ---- load entities: ents[j][d] = ctx[(j*4+d)*BATCH + b] ----
    for (int k = t; k < NUM_ENT * 4; k += THREADS)
        s_ents[k] = ctx[k * BATCH + b];
    __syncthreads();

    // ---- per-thread weight pairs ----
    float2 wr[5], wp[4];
#pragma unroll
    for (int d = 0; d < 5; d++) wr[d] = reinterpret_cast<const float2*>(Wr + d * HALF)[hp];
#pragma unroll
    for (int d = 0; d < 4; d++) wp[d] = reinterpret_cast<const float2*>(Wp + d * HALF)[hp];
    const float2 bp2 = reinterpret_cast<const float2*>(bp)[hp];
    const float2 br2 = reinterpret_cast<const float2*>(br)[hp];

    // ---- phase A: a[j][h] (fp16 table + fp32 block rows)
    //      + partials s1,s2,s3 and W0=Σ|e|²a, W1x=Σe_x a, W1y=Σe_y a ----
    {
        float m10 = 0.f, m11 = 0.f, m20 = 0.f, m21 = 0.f, m30 = 0.f, m31 = 0.f;
        float w00 = 0.f, w01 = 0.f, wx0 = 0.f, wx1 = 0.f, wy0 = 0.f, wy1 = 0.f;
        for (int j = grp; j < NUM_ENT; j += 4) {
            const float* e = s_ents + j * 4;
            const float e0 = e[0], e1 = e[1], e2 = e[2], e3 = e[3];
            const float a0 = e0 * wr[0].x + e1 * wr[1].x + e2 * wr[2].x + e3 * wr[3].x;
            const float a1 = e0 * wr[0].y + e1 * wr[1].y + e2 * wr[2].y + e3 * wr[3].y;
            s_a16[j * 64 + hp] = __floats2half2_rn(a0, a1);
            const unsigned ji = (unsigned)(j - iBase);
            if (ji < (unsigned)I_PER_BLK)
                *reinterpret_cast<float2*>(&s_apre[ji * HALF + 2 * hp]) = make_float2(a0, a1);
            const float q0 = a0 * a0, q1 = a1 * a1;
            const float n2 = e0 * e0 + e1 * e1;
            m10 += a0;       m11 += a1;
            m20 += q0;       m21 += q1;
            m30 += q0 * a0;  m31 += q1 * a1;
            w00 += n2 * a0;  w01 += n2 * a1;
            wx0 += e0 * a0;  wx1 += e0 * a1;
            wy0 += e1 * a0;  wy1 += e1 * a1;
        }
        s_P[grp][hp]      = make_float2(m10, m11);
        s_P[4 + grp][hp]  = make_float2(m20, m21);
        s_P[8 + grp][hp]  = make_float2(m30, m31);
        s_P[12 + grp][hp] = make_float2(w00, w01);
        s_P[16 + grp][hp] = make_float2(wx0, wx1);
        s_P[20 + grp][hp] = make_float2(wy0, wy1);
    }

    // ---- phase B: half2 (d,d) table + fp32 row sums Σd, Σd², Σd³ ----
#pragma unroll
    for (int r = 0; r < 2; r++) {
        const int ii = wid + r * 8;
        const int i  = iBase + ii;
        const float ix = s_ents[i * 4 + 0], iy = s_ents[i * 4 + 1];
        float t0 = 0.f, u0 = 0.f, v0 = 0.f;
#pragma unroll
        for (int c = 0; c < 2; c++) {
            const int j = lane + c * 32;
            const float dx = ix - s_ents[j * 4 + 0];
            const float dy = iy - s_ents[j * 4 + 1];
            const float d2v = dx * dx + dy * dy;     // 0 on diagonal
            const float d   = sqrtf(d2v);
            s_dd[ii * NUM_ENT + j] = __float2half2_rn(d);
            t0 += d; u0 += d2v; v0 += d2v * d;
        }
#pragma unroll
        for (int s = 16; s > 0; s >>= 1) {
            t0 += __shfl_xor_sync(0xffffffffu, t0, s);
            u0 += __shfl_xor_sync(0xffffffffu, u0, s);
            v0 += __shfl_xor_sync(0xffffffffu, v0, s);
        }
        if (lane == 0) { s_T0[ii] = t0; s_U0[ii] = u0; s_V0[ii] = v0; }
    }

    // ---- phase C: property embedding (fp32, deg-7 tanh) ----
#pragma unroll
    for (int kk = 0; kk < 4; kk++) {
        const int i = iBase + grp * 4 + kk;
        const float* e = s_ents + i * 4;
        const float p0 = bp2.x + e[0] * wp[0].x + e[1] * wp[1].x + e[2] * wp[2].x + e[3] * wp[3].x;
        const float p1 = bp2.y + e[0] * wp[0].y + e[1] * wp[1].y + e[2] * wp[2].y + e[3] * wp[3].y;
        const ull xp = pk(p0, p1);
        const ull x2 = mul2(xp, xp);
        ull q = fma2(x2, pkc(-0.05396825f), pkc(0.13333334f));
        q = fma2(x2, q, pkc(-0.33333334f));
        q = fma2(x2, q, pkc(1.0f));
        reinterpret_cast<float2*>(out + (size_t)(b * NUM_ENT + i) * 2 * HALF)[hp]
            = upk(mul2(xp, q));
    }
    __syncthreads();

    // ---- phase D: fp16 moments T1=Σd·a, T2=Σd·a² (U1 is closed-form now) ----
    const int ii0 = grp * 4;
    __half2 t1[4], t2[4];
    const __half2 hz = __float2half2_rn(0.f);
#pragma unroll
    for (int kk = 0; kk < 4; kk++) { t1[kk] = hz; t2[kk] = hz; }

    const __half2* a16 = s_a16 + hp;
    const __half2* ddp = s_dd + ii0 * NUM_ENT;

#pragma unroll 8
    for (int j = 0; j < NUM_ENT; j++) {
        const __half2 aj  = a16[j * 64];               // LDS.32, conflict-free
        const __half2 a2j = __hmul2(aj, aj);
#pragma unroll
        for (int kk = 0; kk < 4; kk++) {
            const __half2 dd = ddp[kk * NUM_ENT + j];  // broadcast LDS.32
            t1[kk] = __hfma2(dd, aj,  t1[kk]);
            t2[kk] = __hfma2(dd, a2j, t2[kk]);
        }
    }

    // ---- epilogue: closed-form Σ tanh(x) ≈ Σx + c3·Σx³ (fp32) ----
    ull s1p, s2p, s3p, W0p, W1xp, W1yp;
    {
#define COMB(dst, base) { \
        const float2 p0 = s_P[(base)][hp], p1 = s_P[(base)+1][hp], \
                     p2 = s_P[(base)+2][hp], p3 = s_P[(base)+3][hp]; \
        dst = add2(add2(pk(p0.x, p0.y), pk(p1.x, p1.y)), \
                   add2(pk(p2.x, p2.y), pk(p3.x, p3.y))); }
        COMB(s1p, 0) COMB(s2p, 4) COMB(s3p, 8)
        COMB(W0p, 12) COMB(W1xp, 16) COMB(W1yp, 20)
#undef COMB
    }
    const ull brp   = pk(br2.x, br2.y);
    const ull w4    = pk(wr[4].x, wr[4].y);
    const ull m3s1  = mul2(s1p, pkc(-3.0f));
    const ull t3s2  = mul2(s2p, pkc(3.0f));
    const ull negs3 = sub2(pkc(0.0f), s3p);
    const ull negs1 = sub2(pkc(0.0f), s1p);
    const ull w42   = mul2(w4, w4);
    const ull t3w4  = mul2(w4,  pkc(3.0f));
    const ull t3w42 = mul2(w42, pkc(3.0f));
    const ull w43   = mul2(w42, w4);
    const ull C3p   = pkc(TANH_C3);
    ull negCorr;   // remove diagonal x_ii = br -> br + c3*br^3
    {
        const ull b3 = mul2(mul2(brp, brp), brp);
        negCorr = sub2(pkc(0.0f), fma2(b3, C3p, brp));
    }

#pragma unroll
    for (int kk = 0; kk < 4; kk++) {
        const int ii = ii0 + kk;
        const int i  = iBase + ii;
        const ull ai  = *reinterpret_cast<const ull*>(&s_apre[ii * HALF + 2 * hp]);
        const ull pre = add2(ai, brp);
        const float T0 = s_T0[ii], U0 = s_U0[ii], V0 = s_V0[ii];
        const ull T0p = pk(T0, T0), U0p = pk(U0, U0), V0p = pk(V0, V0);

        const float2 T1f = __half22float2(t1[kk]);
        const float2 T2f = __half22float2(t2[kk]);
        const ull T1p = pk(T1f.x, T1f.y);
        const ull T2p = pk(T2f.x, T2f.y);

        // U1 closed form: n2_i*s1 + W0 - 2 e_ix W1x - 2 e_iy W1y  (exact fp32)
        const float ex = s_ents[i * 4 + 0], ey = s_ents[i * 4 + 1];
        const float n2i = ex * ex + ey * ey;
        ull U1p = fma2(pk(n2i, n2i), s1p, W0p);
        U1p = fma2(pk(-2.f * ex, -2.f * ex), W1xp, U1p);
        U1p = fma2(pk(-2.f * ey, -2.f * ey), W1yp, U1p);

        const ull pre2 = mul2(pre, pre);
        const ull pre3 = mul2(pre2, pre);
        // A = 64 pre^3 - 3 pre^2 s1 + 3 pre s2 - s3
        ull A = fma2(pre, t3s2, negs3);
        A = fma2(pre2, m3s1, A);
        A = fma2(pre3, pkc(64.0f), A);
        // B = pre^2 T0 - 2 pre T1 + T2
        const ull pm2 = add2(pre, pre);
        ull Bt = sub2(T2p, mul2(pm2, T1p));
        Bt = fma2(pre2, T0p, Bt);
        // C = pre U0 - U1
        const ull Ct = sub2(mul2(pre, U0p), U1p);
        // Sx3 = A + 3 w4 B + 3 w4^2 C + w4^3 V0
        ull S3 = fma2(t3w4, Bt, A);
        S3 = fma2(t3w42, Ct, S3);
        S3 = fma2(w43, V0p, S3);
        // Sx = 64 pre - s1 + w4 T0
        ull Sx = fma2(pre, pkc(64.0f), negs1);
        Sx = fma2(w4, T0p, Sx);
        // result = Sx + c3*Sx3 - corr
        const ull res = fma2(S3, C3p, add2(Sx, negCorr));
        reinterpret_cast<float2*>(out + (size_t)(b * NUM_ENT + i) * 2 * HALF + HALF)[hp]
            = upk(res);
    }
}

extern "C" void kernel_launch(void* const* d_in, const int* in_sizes, int n_in,
                              void* d_out, int out_size)
{
    const float* ctx = (const float*)d_in[0];
    const float* Wp  = (const float*)d_in[1];
    const float* bp  = (const float*)d_in[2];
    const float* Wr  = (const float*)d_in[3];
    const float* br  = (const float*)d_in[4];
    float* out = (float*)d_out;

    ace_kernel<<<BATCH * 4, THREADS>>>(ctx, Wp, bp, Wr, br, out);
}

// round 14
// speedup vs baseline: 2.2276x; 2.2276x over previous
#include <cuda_runtime.h>
#include <cuda_fp16.h>
#include <cstdint>

#define NUM_ENT 64
#define HALF    128
#define BATCH   512
#define THREADS 256

typedef unsigned long long ull;

// ---------------- dynamic smem layout (bytes) ----------------
#define OFF_ENTS 0                  // float[64*4]
#define OFF_EX   1024               // float[64]
#define OFF_EY   1280               // float[64]
#define OFF_T0   1536               // float[64]
#define OFF_U0   1792               // float[64]
#define OFF_V0   2048               // float[64]
#define OFF_SC   2304               // ull[3][64] : s1p, s2p, s3p
#define OFF_P    3840               // float2[12][64] partials
#define OFF_D16  9984               // half[64][72]  : d
#define OFF_Q16  19200              // half[64][72]  : d^2
#define OFF_A16  28416              // half[64][136] : a
#define OFF_A2   45824              // half[64][136] : a^2
#define SMEM_TOTAL 63232

// ---- packed f32x2 helpers ---------------------------------------------------
__device__ __forceinline__ ull pk(float lo, float hi) {
    ull r; asm("mov.b64 %0, {%1,%2};" : "=l"(r) : "f"(lo), "f"(hi)); return r;
}
__device__ __forceinline__ ull pkc(float v) {
    unsigned u = __float_as_uint(v);
    return ((ull)u << 32) | (ull)u;
}
__device__ __forceinline__ float2 upk(ull v) {
    float2 r; asm("mov.b64 {%0,%1}, %2;" : "=f"(r.x), "=f"(r.y) : "l"(v)); return r;
}
__device__ __forceinline__ ull fma2(ull a, ull b, ull c) {
    ull d; asm("fma.rn.f32x2 %0, %1, %2, %3;" : "=l"(d) : "l"(a), "l"(b), "l"(c)); return d;
}
__device__ __forceinline__ ull add2(ull a, ull b) {
    ull d; asm("add.rn.f32x2 %0, %1, %2;" : "=l"(d) : "l"(a), "l"(b)); return d;
}
__device__ __forceinline__ ull sub2(ull a, ull b) {
    ull d; asm("sub.rn.f32x2 %0, %1, %2;" : "=l"(d) : "l"(a), "l"(b)); return d;
}
__device__ __forceinline__ ull mul2(ull a, ull b) {
    ull d; asm("mul.rn.f32x2 %0, %1, %2;" : "=l"(d) : "l"(a), "l"(b)); return d;
}
#define TANH_C3 (-0.33333334f)

// ---- tensor-core wrappers (Ampere-class, valid on plain sm_103) -------------
__device__ __forceinline__ void ldsm_x4(uint32_t* r, uint32_t addr) {
    asm volatile("ldmatrix.sync.aligned.m8n8.x4.shared.b16 {%0,%1,%2,%3}, [%4];"
                 : "=r"(r[0]), "=r"(r[1]), "=r"(r[2]), "=r"(r[3]) : "r"(addr));
}
__device__ __forceinline__ void ldsm_x2t(uint32_t& r0, uint32_t& r1, uint32_t addr) {
    asm volatile("ldmatrix.sync.aligned.m8n8.x2.trans.shared.b16 {%0,%1}, [%2];"
                 : "=r"(r0), "=r"(r1) : "r"(addr));
}
__device__ __forceinline__ void mma16816(float* c, const uint32_t* a,
                                         uint32_t b0, uint32_t b1) {
    asm volatile(
        "mma.sync.aligned.m16n8k16.row.col.f32.f16.f16.f32 "
        "{%0,%1,%2,%3}, {%4,%5,%6,%7}, {%8,%9}, {%0,%1,%2,%3};"
        : "+f"(c[0]), "+f"(c[1]), "+f"(c[2]), "+f"(c[3])
        : "r"(a[0]), "r"(a[1]), "r"(a[2]), "r"(a[3]), "r"(b0), "r"(b1));
}

__global__ __launch_bounds__(THREADS, 3)
void ace_kernel(const float* __restrict__ ctx,   // [NUM_ENT*4, BATCH]
                const float* __restrict__ Wp,    // [4, HALF]
                const float* __restrict__ bp,    // [HALF]
                const float* __restrict__ Wr,    // [5, HALF]
                const float* __restrict__ br,    // [HALF]
                float* __restrict__ out)         // [BATCH, NUM_ENT, 2*HALF]
{
    extern __shared__ char smem[];
    float* smf = reinterpret_cast<float*>(smem);

    const int b    = blockIdx.x;
    const int t    = threadIdx.x;
    const int w    = t >> 5;
    const int lane = t & 31;
    const int hp   = t & 63;
    const int grp  = t >> 6;

    // ---- load entities ----
    for (int k = t; k < NUM_ENT * 4; k += THREADS) {
        const float v = ctx[k * BATCH + b];
        smf[OFF_ENTS / 4 + k] = v;
        const int j = k >> 2, d = k & 3;
        if (d == 0) smf[OFF_EX / 4 + j] = v;
        if (d == 1) smf[OFF_EY / 4 + j] = v;
    }
    __syncthreads();

    // ---- per-thread weight pairs (phases A/C) ----
    float2 wrv[4], wpv[4];
#pragma unroll
    for (int d = 0; d < 4; d++) {
        wrv[d] = reinterpret_cast<const float2*>(Wr + d * HALF)[hp];
        wpv[d] = reinterpret_cast<const float2*>(Wp + d * HALF)[hp];
    }
    const float2 bp2 = reinterpret_cast<const float2*>(bp)[hp];

    // ---- phase A: a (fp16 + a^2 fp16 tables) + fp32 partials s1,s2,s3 ----
    {
        float m10 = 0.f, m11 = 0.f, m20 = 0.f, m21 = 0.f, m30 = 0.f, m31 = 0.f;
        for (int j = grp; j < NUM_ENT; j += 4) {
            const float* e = smf + OFF_ENTS / 4 + j * 4;
            const float a0 = e[0] * wrv[0].x + e[1] * wrv[1].x + e[2] * wrv[2].x + e[3] * wrv[3].x;
            const float a1 = e[0] * wrv[0].y + e[1] * wrv[1].y + e[2] * wrv[2].y + e[3] * wrv[3].y;
            *reinterpret_cast<__half2*>(smem + OFF_A16 + (j * 136 + 2 * hp) * 2)
                = __floats2half2_rn(a0, a1);
            *reinterpret_cast<__half2*>(smem + OFF_A2 + (j * 136 + 2 * hp) * 2)
                = __floats2half2_rn(a0 * a0, a1 * a1);
            const float q0 = a0 * a0, q1 = a1 * a1;
            m10 += a0;      m11 += a1;
            m20 += q0;      m21 += q1;
            m30 += q0 * a0; m31 += q1 * a1;
        }
        float2* P = reinterpret_cast<float2*>(smem + OFF_P);
        P[grp * 64 + hp]       = make_float2(m10, m11);
        P[(4 + grp) * 64 + hp] = make_float2(m20, m21);
        P[(8 + grp) * 64 + hp] = make_float2(m30, m31);
    }

    // ---- phase B: d / d^2 fp16 tiles + fp32 row sums T0,U0,V0 ----
#pragma unroll
    for (int r = 0; r < 8; r++) {
        const int i = w * 8 + r;
        const float ix = smf[OFF_EX / 4 + i], iy = smf[OFF_EY / 4 + i];
        const int j0 = 2 * lane, j1 = j0 + 1;
        const float dxa = ix - smf[OFF_EX / 4 + j0], dya = iy - smf[OFF_EY / 4 + j0];
        const float dxb = ix - smf[OFF_EX / 4 + j1], dyb = iy - smf[OFF_EY / 4 + j1];
        const float d2a = dxa * dxa + dya * dya;
        const float d2b = dxb * dxb + dyb * dyb;
        const float da = sqrtf(d2a), db = sqrtf(d2b);
        *reinterpret_cast<__half2*>(smem + OFF_D16 + (i * 72 + j0) * 2)
            = __floats2half2_rn(da, db);
        *reinterpret_cast<__half2*>(smem + OFF_Q16 + (i * 72 + j0) * 2)
            = __floats2half2_rn(d2a, d2b);
        float t0 = da + db, u0 = d2a + d2b, v0 = d2a * da + d2b * db;
#pragma unroll
        for (int s = 16; s > 0; s >>= 1) {
            t0 += __shfl_xor_sync(0xffffffffu, t0, s);
            u0 += __shfl_xor_sync(0xffffffffu, u0, s);
            v0 += __shfl_xor_sync(0xffffffffu, v0, s);
        }
        if (lane == 0) {
            smf[OFF_T0 / 4 + i] = t0;
            smf[OFF_U0 / 4 + i] = u0;
            smf[OFF_V0 / 4 + i] = v0;
        }
    }

    // ---- phase C: property embedding (fp32, deg-7 tanh) ----
    for (int k = 0; k < 16; k++) {
        const int i = grp + 4 * k;
        const float* e = smf + OFF_ENTS / 4 + i * 4;
        const float p0 = bp2.x + e[0] * wpv[0].x + e[1] * wpv[1].x + e[2] * wpv[2].x + e[3] * wpv[3].x;
        const float p1 = bp2.y + e[0] * wpv[0].y + e[1] * wpv[1].y + e[2] * wpv[2].y + e[3] * wpv[3].y;
        const ull xp = pk(p0, p1);
        const ull x2 = mul2(xp, xp);
        ull q = fma2(x2, pkc(-0.05396825f), pkc(0.13333334f));
        q = fma2(x2, q, pkc(-0.33333334f));
        q = fma2(x2, q, pkc(1.0f));
        reinterpret_cast<float2*>(out + (size_t)(b * NUM_ENT + i) * 2 * HALF)[hp]
            = upk(mul2(xp, q));
    }
    __syncthreads();

    // ---- combine partials into per-h packed tables ----
    if (t < 64) {
        const float2* P = reinterpret_cast<const float2*>(smem + OFF_P);
        ull* SC = reinterpret_cast<ull*>(smem + OFF_SC);
#pragma unroll
        for (int m = 0; m < 3; m++) {
            float sx = 0.f, sy = 0.f;
#pragma unroll
            for (int g = 0; g < 4; g++) {
                const float2 v = P[(m * 4 + g) * 64 + t];
                sx += v.x; sy += v.y;
            }
            SC[m * 64 + t] = pk(sx, sy);
        }
    }
    __syncthreads();

    // ---- phase D: moments T1=d·a, T2=d·a², U1=d²·a via mma.sync ----
    const uint32_t sb = (uint32_t)__cvta_generic_to_shared(smem);
    const int h0w = w * 16;
    const int fr  = lane >> 2;          // fragment row 0..7
    const int fc  = (lane & 3) * 2;     // fragment col 0,2,4,6
    const int arow = (lane & 7) + ((lane & 8) ? 8 : 0);
    const int acol = (lane & 16) ? 8 : 0;
    const int brow_off = (lane & 7) + ((lane & 8) ? 8 : 0);
    const ull C3p = pkc(TANH_C3);

    for (int mt = 0; mt < 4; mt++) {
        const int i0 = mt * 16;
        float c1[2][4], c2[2][4], c3[2][4];
#pragma unroll
        for (int nt = 0; nt < 2; nt++)
#pragma unroll
            for (int q = 0; q < 4; q++) { c1[nt][q] = 0.f; c2[nt][q] = 0.f; c3[nt][q] = 0.f; }

#pragma unroll
        for (int k = 0; k < 4; k++) {
            const int j0 = k * 16;
            uint32_t dA[4], qA[4];
            const uint32_t offA = ((i0 + arow) * 72 + j0 + acol) * 2;
            ldsm_x4(dA, sb + OFF_D16 + offA);
            ldsm_x4(qA, sb + OFF_Q16 + offA);
            const int brj = j0 + brow_off;
#pragma unroll
            for (int nt = 0; nt < 2; nt++) {
                const int h0 = h0w + nt * 8;
                uint32_t bA0, bA1, bQ0, bQ1;
                ldsm_x2t(bA0, bA1, sb + OFF_A16 + (brj * 136 + h0) * 2);
                ldsm_x2t(bQ0, bQ1, sb + OFF_A2  + (brj * 136 + h0) * 2);
                mma16816(c1[nt], dA, bA0, bA1);
                mma16816(c2[nt], dA, bQ0, bQ1);
                mma16816(c3[nt], qA, bA0, bA1);
            }
        }

        // ---- epilogue for this m-tile ----
        float ev[2][4];
#pragma unroll
        for (int ih = 0; ih < 2; ih++) {
            const int i = i0 + fr + ih * 8;
#pragma unroll
            for (int d = 0; d < 4; d++) ev[ih][d] = smf[OFF_ENTS / 4 + i * 4 + d];
        }

#pragma unroll
        for (int nt = 0; nt < 2; nt++) {
            const int hq = (h0w + nt * 8 + fc) >> 1;
            const float2 r0 = __ldg(reinterpret_cast<const float2*>(Wr + 0 * HALF) + hq);
            const float2 r1 = __ldg(reinterpret_cast<const float2*>(Wr + 1 * HALF) + hq);
            const float2 r2 = __ldg(reinterpret_cast<const float2*>(Wr + 2 * HALF) + hq);
            const float2 r3 = __ldg(reinterpret_cast<const float2*>(Wr + 3 * HALF) + hq);
            const float2 w4v = __ldg(reinterpret_cast<const float2*>(Wr + 4 * HALF) + hq);
            const float2 brv = __ldg(reinterpret_cast<const float2*>(br) + hq);
            const ull* SC = reinterpret_cast<const ull*>(smem + OFF_SC);
            const ull s1p = SC[0 * 64 + hq];
            const ull s2p = SC[1 * 64 + hq];
            const ull s3p = SC[2 * 64 + hq];
            const ull w4p = pk(w4v.x, w4v.y);
            const ull brp = pk(brv.x, brv.y);
            const ull m3s1  = mul2(s1p, pkc(-3.0f));
            const ull t3s2  = mul2(s2p, pkc(3.0f));
            const ull negs1 = sub2(pkc(0.0f), s1p);
            const ull negs3 = sub2(pkc(0.0f), s3p);
            const ull w42   = mul2(w4p, w4p);
            const ull t3w4  = mul2(w4p, pkc(3.0f));
            const ull t3w42 = mul2(w42, pkc(3.0f));
            const ull w43   = mul2(w42, w4p);
            const ull br3   = mul2(mul2(brp, brp), brp);
            const ull corr  = fma2(br3, C3p, brp);     // tanh(br) approx

#pragma unroll
            for (int ih = 0; ih < 2; ih++) {
                const int i = i0 + fr + ih * 8;
                const float* e = ev[ih];
                const float a0 = e[0] * r0.x + e[1] * r1.x + e[2] * r2.x + e[3] * r3.x;
                const float a1 = e[0] * r0.y + e[1] * r1.y + e[2] * r2.y + e[3] * r3.y;
                const ull pre = add2(pk(a0, a1), brp);
                const ull T1p = pk(c1[nt][ih * 2], c1[nt][ih * 2 + 1]);
                const ull T2p = pk(c2[nt][ih * 2], c2[nt][ih * 2 + 1]);
                const ull U1p = pk(c3[nt][ih * 2], c3[nt][ih * 2 + 1]);
                const float T0 = smf[OFF_T0 / 4 + i];
                const float U0 = smf[OFF_U0 / 4 + i];
                const float V0 = smf[OFF_V0 / 4 + i];
                const ull T0p = pk(T0, T0), U0p = pk(U0, U0), V0p = pk(V0, V0);

                const ull pre2 = mul2(pre, pre);
                // A = ((64 pre - 3 s1) pre + 3 s2) pre - s3
                ull A = fma2(pre, pkc(64.0f), m3s1);
                A = fma2(A, pre, t3s2);
                A = fma2(A, pre, negs3);
                // B' = pre^2 T0 - 2 pre T1 + T2
                ull Bt = fma2(mul2(pre, T1p), pkc(-2.0f), T2p);
                Bt = fma2(pre2, T0p, Bt);
                // C' = pre U0 - U1
                const ull Ct = sub2(mul2(pre, U0p), U1p);
                // S3 = A + 3 w4 B' + 3 w4^2 C' + w4^3 V0
                ull S3 = fma2(t3w4, Bt, A);
                S3 = fma2(t3w42, Ct, S3);
                S3 = fma2(w43, V0p, S3);
                // Sx = 64 pre - s1 + w4 T0
                ull Sx = fma2(pre, pkc(64.0f), negs1);
                Sx = fma2(w4p, T0p, Sx);
                // res = Sx + c3*S3 - corr
                const ull res = fma2(S3, C3p, sub2(Sx, corr));
                *reinterpret_cast<float2*>(
                    out + (size_t)(b * NUM_ENT + i) * 2 * HALF + HALF + 2 * hq) = upk(res);
            }
        }
    }
}

extern "C" void kernel_launch(void* const* d_in, const int* in_sizes, int n_in,
                              void* d_out, int out_size)
{
    const float* ctx = (const float*)d_in[0];
    const float* Wp  = (const float*)d_in[1];
    const float* bp  = (const float*)d_in[2];
    const float* Wr  = (const float*)d_in[3];
    const float* br  = (const float*)d_in[4];
    float* out = (float*)d_out;

    cudaFuncSetAttribute(ace_kernel, cudaFuncAttributeMaxDynamicSharedMemorySize, SMEM_TOTAL);
    ace_kernel<<<BATCH, THREADS, SMEM_TOTAL>>>(ctx, Wp, bp, Wr, br, out);
}